// round 9
// baseline (speedup 1.0000x reference)
#include <cuda_runtime.h>

// ---------------------------------------------------------------------------
// GAT, B=32 N=14 IN=OUT=1024 H=4.
//  kdummy: empty (shifts ncu capture slot onto k2).
//  k1 : Wh = x@W. One CTA per (hb, col-half). Full K per CTA. (R6 version)
//  k1b: a-dots + masked softmax + h_prime = att@Wh -> g_hp  (R6 version)
//  k2 : out partials = h_prime @ fc_w^T. NEW: 8o x 8b per thread, 128 thr,
//       chunk-8 double buffer, sector-exact hp staging.
//  k3a: reduce 64 partials + bias. k3b: log_softmax.       (R6 versions)
// ---------------------------------------------------------------------------

#define NEGC -9e15f

__device__ __forceinline__ float2 ffma2(float2 a, float2 b, float2 c) {
    float2 d;
    asm("fma.rn.f32x2 %0, %1, %2, %3;"
        : "=l"(*reinterpret_cast<unsigned long long*>(&d))
        : "l"(*reinterpret_cast<unsigned long long*>(&a)),
          "l"(*reinterpret_cast<unsigned long long*>(&b)),
          "l"(*reinterpret_cast<unsigned long long*>(&c)));
    return d;
}

// scratch
__device__ float g_wh[128 * 14 * 1024];        // Wh      (hb, n, c)
__device__ float g_hp[128 * 14 * 1024];        // h_prime (hb, n, c)
__device__ float g_part[64 * 32 * 1024];       // out partials (h*16+ks, b, o)
__device__ float g_red[32 * 1024];             // reduced logits

__global__ void kdummy() {}

// ---------------------------------------------------------------------------
// k1 (R6): grid 256 = (hb 128) x (col-half 2). 256 threads, 2 cols/thread,
// full K=1024. dyn smem 64KB: x transposed [k*16 + n].
// ---------------------------------------------------------------------------
__global__ __launch_bounds__(256, 2) void k1(
    const float* __restrict__ x, const float* __restrict__ W)
{
    extern __shared__ float s_x[];              // [k*16 + n], 65536 B

    const int tid = threadIdx.x;
    const int hb  = blockIdx.x >> 1;
    const int ch  = blockIdx.x & 1;
    const int b   = hb & 31;
    const int c0  = ch * 512 + tid * 2;

    const float* xb = x + (size_t)b * 14336;
    for (int idx = tid; idx < 14336; idx += 256) {
        int n = idx >> 10, k = idx & 1023;
        s_x[k * 16 + n] = xb[idx];
    }
    __syncthreads();

    const float* Wp = W + ((size_t)hb << 20) + c0;

    float2 acc[7][2];
    #pragma unroll
    for (int p = 0; p < 7; p++) {
        acc[p][0] = make_float2(0.f, 0.f);
        acc[p][1] = make_float2(0.f, 0.f);
    }

    float2 wc[8];
    #pragma unroll
    for (int u = 0; u < 8; u++)
        wc[u] = *(const float2*)(Wp + (size_t)u * 1024);

    #pragma unroll 1
    for (int k0 = 0; k0 < 1024; k0 += 8) {
        float2 wn[8];
        if (k0 + 8 < 1024) {
            #pragma unroll
            for (int u = 0; u < 8; u++)
                wn[u] = *(const float2*)(Wp + (size_t)(k0 + 8 + u) * 1024);
        }
        #pragma unroll
        for (int u = 0; u < 8; u++) {
            const float* xr = &s_x[(k0 + u) * 16];
            float4 xa = *(const float4*)(xr);
            float4 xb4 = *(const float4*)(xr + 4);
            float4 xc = *(const float4*)(xr + 8);
            float2 xd = *(const float2*)(xr + 12);
            float2 xp[7];
            xp[0] = make_float2(xa.x, xa.y);   xp[1] = make_float2(xa.z, xa.w);
            xp[2] = make_float2(xb4.x, xb4.y); xp[3] = make_float2(xb4.z, xb4.w);
            xp[4] = make_float2(xc.x, xc.y);   xp[5] = make_float2(xc.z, xc.w);
            xp[6] = xd;
            float2 s0 = make_float2(wc[u].x, wc[u].x);
            float2 s1 = make_float2(wc[u].y, wc[u].y);
            #pragma unroll
            for (int p = 0; p < 7; p++) {
                acc[p][0] = ffma2(xp[p], s0, acc[p][0]);
                acc[p][1] = ffma2(xp[p], s1, acc[p][1]);
            }
        }
        #pragma unroll
        for (int u = 0; u < 8; u++) wc[u] = wn[u];
    }

    float* dst = g_wh + (size_t)hb * 14336 + c0;
    #pragma unroll
    for (int p = 0; p < 7; p++) {
        *(float2*)(dst + (size_t)(2 * p) * 1024)     = make_float2(acc[p][0].x, acc[p][1].x);
        *(float2*)(dst + (size_t)(2 * p + 1) * 1024) = make_float2(acc[p][0].y, acc[p][1].y);
    }
}

// ---------------------------------------------------------------------------
// k1b (R6): grid 128 (hb), 256 threads. a-dots + block reduce; masked
// softmax; h_prime = att @ Wh; write g_hp.
// ---------------------------------------------------------------------------
__global__ __launch_bounds__(256, 1) void k1b(
    const float* __restrict__ adj, const float* __restrict__ a)
{
    __shared__ float s_red[8][28];
    __shared__ float s_dot[28];
    __shared__ float s_att[14 * 16];

    const int tid = threadIdx.x;
    const int hb  = blockIdx.x;
    const int b   = hb & 31;
    const int c0  = tid * 4;
    const int wid = tid >> 5, lane = tid & 31;

    float4 wh[14];
    const float* p0 = g_wh + (size_t)hb * 14336 + c0;
    #pragma unroll
    for (int n = 0; n < 14; n++)
        wh[n] = *(const float4*)(p0 + n * 1024);

    float4 a1 = *(const float4*)(a + (size_t)hb * 2048 + c0);
    float4 a2 = *(const float4*)(a + (size_t)hb * 2048 + 1024 + c0);
    float s1[14], s2[14];
    #pragma unroll
    for (int n = 0; n < 14; n++) {
        s1[n] = wh[n].x * a1.x + wh[n].y * a1.y + wh[n].z * a1.z + wh[n].w * a1.w;
        s2[n] = wh[n].x * a2.x + wh[n].y * a2.y + wh[n].z * a2.z + wh[n].w * a2.w;
    }
    #pragma unroll
    for (int n = 0; n < 14; n++) {
        #pragma unroll
        for (int off = 16; off > 0; off >>= 1) {
            s1[n] += __shfl_down_sync(0xFFFFFFFFu, s1[n], off);
            s2[n] += __shfl_down_sync(0xFFFFFFFFu, s2[n], off);
        }
    }
    if (lane == 0) {
        #pragma unroll
        for (int n = 0; n < 14; n++) { s_red[wid][n] = s1[n]; s_red[wid][14 + n] = s2[n]; }
    }
    __syncthreads();
    if (tid < 28) {
        float s = 0.f;
        #pragma unroll
        for (int w = 0; w < 8; w++) s += s_red[w][tid];
        s_dot[tid] = s;
    }
    __syncthreads();

    if (tid < 196) {
        int n = tid / 14, m = tid - n * 14;
        float e = s_dot[n] + s_dot[14 + m];
        e = (e > 0.f) ? e : 0.2f * e;
        float ad = adj[b * 196 + n * 14 + m];
        s_att[m * 16 + n] = (ad > 0.f) ? e : NEGC;
    }
    __syncthreads();

    if (tid < 14) {
        const int m = tid;
        float mx = -3.4e38f, ev[14], s = 0.f;
        #pragma unroll
        for (int n = 0; n < 14; n++) mx = fmaxf(mx, s_att[m * 16 + n]);
        #pragma unroll
        for (int n = 0; n < 14; n++) { ev[n] = expf(s_att[m * 16 + n] - mx); s += ev[n]; }
        float inv = 1.f / s;
        #pragma unroll
        for (int n = 0; n < 14; n++) s_att[m * 16 + n] = ev[n] * inv;
    }
    __syncthreads();

    float2 hp[7][4];
    #pragma unroll
    for (int p = 0; p < 7; p++)
        #pragma unroll
        for (int c = 0; c < 4; c++) hp[p][c] = make_float2(0.f, 0.f);

    #pragma unroll
    for (int m = 0; m < 14; m++) {
        float2 t0 = make_float2(wh[m].x, wh[m].x);
        float2 t1 = make_float2(wh[m].y, wh[m].y);
        float2 t2 = make_float2(wh[m].z, wh[m].z);
        float2 t3 = make_float2(wh[m].w, wh[m].w);
        #pragma unroll
        for (int p = 0; p < 7; p++) {
            float2 at = *(const float2*)&s_att[m * 16 + 2 * p];
            hp[p][0] = ffma2(at, t0, hp[p][0]);
            hp[p][1] = ffma2(at, t1, hp[p][1]);
            hp[p][2] = ffma2(at, t2, hp[p][2]);
            hp[p][3] = ffma2(at, t3, hp[p][3]);
        }
    }
    float* hpg = g_hp + (size_t)hb * 14336;
    #pragma unroll
    for (int p = 0; p < 7; p++) {
        *(float4*)&hpg[(2 * p) * 1024 + c0] =
            make_float4(hp[p][0].x, hp[p][1].x, hp[p][2].x, hp[p][3].x);
        *(float4*)&hpg[(2 * p + 1) * 1024 + c0] =
            make_float4(hp[p][0].y, hp[p][1].y, hp[p][2].y, hp[p][3].y);
    }
}

// ---------------------------------------------------------------------------
// k2 NEW: grid (64, 4) = (ks*4+ot, h), 128 threads, occ 4.
// CTA tile: 256 o x 32 b, k-span 896, chunk 8, double buffered.
// Thread: 8 o (4 float2, o = obase + 2*lane + 64q) x 8 b (b = w*8+j).
// ---------------------------------------------------------------------------
__global__ __launch_bounds__(128, 4) void k2(const float* __restrict__ fcw)
{
    __shared__ float s_w[2][8 * 256];           // [buf][k][o]
    __shared__ float s_hp[2][8 * 32];           // [buf][k][b]

    const int tid  = threadIdx.x;
    const int lane = tid & 31;
    const int w    = tid >> 5;                  // 0..3 -> b-group of 8
    const int ks   = blockIdx.x >> 2;
    const int ot   = blockIdx.x & 3;
    const int h    = blockIdx.y;
    const int obase = ot * 256;
    const int kbase = ks * 896;

    // W staging: thread owns o-rows (obase+tid) and (obase+tid+128), 8 k/chunk
    const float* wrA = fcw + ((size_t)(h * 1024 + obase + tid)) * 14336 + kbase;
    const float* wrB = wrA + (size_t)128 * 14336;
    // hp staging: warp 0 only, b = lane, 8 consecutive k (32B sector-exact)
    const float* hpr = g_hp + ((size_t)(h * 32 + lane)) * 14336 + kbase;

    float2 acc[4][8];
    #pragma unroll
    for (int q = 0; q < 4; q++)
        #pragma unroll
        for (int j = 0; j < 8; j++) acc[q][j] = make_float2(0.f, 0.f);

    // prologue: chunk 0 -> buffer 0
    {
        float4 va0 = *(const float4*)(wrA);
        float4 va1 = *(const float4*)(wrA + 4);
        float4 vb0 = *(const float4*)(wrB);
        float4 vb1 = *(const float4*)(wrB + 4);
        float aA[8] = {va0.x, va0.y, va0.z, va0.w, va1.x, va1.y, va1.z, va1.w};
        float aB[8] = {vb0.x, vb0.y, vb0.z, vb0.w, vb1.x, vb1.y, vb1.z, vb1.w};
        #pragma unroll
        for (int kk = 0; kk < 8; kk++) {
            s_w[0][kk * 256 + tid]       = aA[kk];
            s_w[0][kk * 256 + tid + 128] = aB[kk];
        }
        if (w == 0) {
            float4 h0 = *(const float4*)(hpr);
            float4 h1 = *(const float4*)(hpr + 4);
            float hh[8] = {h0.x, h0.y, h0.z, h0.w, h1.x, h1.y, h1.z, h1.w};
            #pragma unroll
            for (int kk = 0; kk < 8; kk++)
                s_hp[0][kk * 32 + lane] = hh[kk];
        }
    }
    __syncthreads();

    #pragma unroll 1
    for (int ck = 0; ck < 112; ck++) {
        const int buf = ck & 1;

        float4 va0, va1, vb0, vb1, h0, h1;
        if (ck + 1 < 112) {
            const int ko = (ck + 1) * 8;
            va0 = *(const float4*)(wrA + ko);
            va1 = *(const float4*)(wrA + ko + 4);
            vb0 = *(const float4*)(wrB + ko);
            vb1 = *(const float4*)(wrB + ko + 4);
            if (w == 0) {
                h0 = *(const float4*)(hpr + ko);
                h1 = *(const float4*)(hpr + ko + 4);
            }
        }

        #pragma unroll
        for (int k = 0; k < 8; k++) {
            float2 af[4];
            #pragma unroll
            for (int q = 0; q < 4; q++)
                af[q] = *(const float2*)&s_w[buf][k * 256 + 2 * lane + 64 * q];
            float4 bf0 = *(const float4*)&s_hp[buf][k * 32 + w * 8];
            float4 bf1 = *(const float4*)&s_hp[buf][k * 32 + w * 8 + 4];
            float bb[8] = {bf0.x, bf0.y, bf0.z, bf0.w, bf1.x, bf1.y, bf1.z, bf1.w};
            #pragma unroll
            for (int j = 0; j < 8; j++) {
                float2 d = make_float2(bb[j], bb[j]);
                #pragma unroll
                for (int q = 0; q < 4; q++)
                    acc[q][j] = ffma2(af[q], d, acc[q][j]);
            }
        }

        if (ck + 1 < 112) {
            const int nb = buf ^ 1;
            float aA[8] = {va0.x, va0.y, va0.z, va0.w, va1.x, va1.y, va1.z, va1.w};
            float aB[8] = {vb0.x, vb0.y, vb0.z, vb0.w, vb1.x, vb1.y, vb1.z, vb1.w};
            #pragma unroll
            for (int kk = 0; kk < 8; kk++) {
                s_w[nb][kk * 256 + tid]       = aA[kk];
                s_w[nb][kk * 256 + tid + 128] = aB[kk];
            }
            if (w == 0) {
                float hh[8] = {h0.x, h0.y, h0.z, h0.w, h1.x, h1.y, h1.z, h1.w};
                #pragma unroll
                for (int kk = 0; kk < 8; kk++)
                    s_hp[nb][kk * 32 + lane] = hh[kk];
            }
            __syncthreads();
        }
    }

    float* dst = g_part + ((size_t)(h * 16 + ks)) * 32768 + obase;
    #pragma unroll
    for (int j = 0; j < 8; j++)
        #pragma unroll
        for (int q = 0; q < 4; q++)
            *(float2*)(dst + (size_t)(w * 8 + j) * 1024 + 2 * lane + 64 * q) = acc[q][j];
}

// ---------------------------------------------------------------------------
// k3a (R6): reduce 64 partials + bias. grid 256, 128 threads.
// ---------------------------------------------------------------------------
__global__ __launch_bounds__(128, 8) void k3a(const float* __restrict__ fcb)
{
    const int b  = blockIdx.x >> 3;
    const int o  = (blockIdx.x & 7) * 128 + threadIdx.x;

    float s = 0.f;
    #pragma unroll 8
    for (int pb = 0; pb < 64; pb++)
        s += g_part[(size_t)pb * 32768 + b * 1024 + o];
    #pragma unroll
    for (int hh = 0; hh < 4; hh++) s += fcb[hh * 1024 + o];
    g_red[b * 1024 + o] = s;
}

// ---------------------------------------------------------------------------
// k3b (R6): log_softmax per b. grid 32, 256 threads.
// ---------------------------------------------------------------------------
__global__ __launch_bounds__(256, 1) void k3b(float* __restrict__ out)
{
    __shared__ float red[256];
    const int b = blockIdx.x, tid = threadIdx.x;

    float4 v = *(const float4*)&g_red[b * 1024 + tid * 4];

    float mx = fmaxf(fmaxf(v.x, v.y), fmaxf(v.z, v.w));
    red[tid] = mx; __syncthreads();
    for (int st = 128; st > 0; st >>= 1) {
        if (tid < st) red[tid] = fmaxf(red[tid], red[tid + st]);
        __syncthreads();
    }
    mx = red[0]; __syncthreads();

    float s = expf(v.x - mx) + expf(v.y - mx) + expf(v.z - mx) + expf(v.w - mx);
    red[tid] = s; __syncthreads();
    for (int st = 128; st > 0; st >>= 1) {
        if (tid < st) red[tid] += red[tid + st];
        __syncthreads();
    }
    float lse = mx + logf(red[0]);

    *(float4*)&out[b * 1024 + tid * 4] =
        make_float4(v.x - lse, v.y - lse, v.z - lse, v.w - lse);
}

// ---------------------------------------------------------------------------
extern "C" void kernel_launch(void* const* d_in, const int* in_sizes, int n_in,
                              void* d_out, int out_size)
{
    const float *x = nullptr, *adj = nullptr, *W = nullptr, *a = nullptr,
                *fcw = nullptr, *fcb = nullptr;
    for (int i = 0; i < n_in; i++) {
        switch (in_sizes[i]) {
            case 32 * 14 * 1024:        x   = (const float*)d_in[i]; break;
            case 32 * 14 * 14:          adj = (const float*)d_in[i]; break;
            case 4 * 32 * 1024 * 1024:  W   = (const float*)d_in[i]; break;
            case 4 * 32 * 2048:         a   = (const float*)d_in[i]; break;
            case 4 * 1024 * 14336:      fcw = (const float*)d_in[i]; break;
            case 4 * 1024:              fcb = (const float*)d_in[i]; break;
            default: break;
        }
    }
    float* out = (float*)d_out;

    cudaFuncSetAttribute(k1, cudaFuncAttributeMaxDynamicSharedMemorySize, 65536);

    kdummy<<<1, 32>>>();
    k1<<<256, 256, 65536>>>(x, W);
    k1b<<<128, 256>>>(adj, a);
    k2<<<dim3(64, 4), 128>>>(fcw);
    k3a<<<256, 128>>>(fcb);
    k3b<<<32, 256>>>(out);
}

// round 13
// speedup vs baseline: 1.1936x; 1.1936x over previous
#include <cuda_runtime.h>

// ---------------------------------------------------------------------------
// GAT, B=32 N=14 IN=OUT=1024 H=4.
//  kdummy: empty (keeps ncu capture slot on k2).
//  k1 : Wh = x@W (R6). k1b: a-dots + softmax + h_prime (R6).
//  k2 : 4-lane/row coalesced W loads (8 wf/LDG.128), chunk 16, bank-exact
//       transpose (row stride 262), grid 512, 8o x 8b compute.
//       FIX vs R10: hp staging uses tid<64 (2 warps) so all 32 b are staged.
//  k3a: reduce 128 partials + bias (4-way). k3b: log_softmax.
// ---------------------------------------------------------------------------

#define NEGC -9e15f

__device__ __forceinline__ float2 ffma2(float2 a, float2 b, float2 c) {
    float2 d;
    asm("fma.rn.f32x2 %0, %1, %2, %3;"
        : "=l"(*reinterpret_cast<unsigned long long*>(&d))
        : "l"(*reinterpret_cast<unsigned long long*>(&a)),
          "l"(*reinterpret_cast<unsigned long long*>(&b)),
          "l"(*reinterpret_cast<unsigned long long*>(&c)));
    return d;
}

// scratch
__device__ float g_wh[128 * 14 * 1024];        // Wh      (hb, n, c)
__device__ float g_hp[128 * 14 * 1024];        // h_prime (hb, n, c)
__device__ float g_part[128 * 32 * 1024];      // out partials (h*32+ks, b, o)
__device__ float g_red[32 * 1024];             // reduced logits

__global__ void kdummy() {}

// ---------------------------------------------------------------------------
// k1 (R6): grid 256 = (hb 128) x (col-half 2). 256 threads, 2 cols/thread,
// full K=1024. dyn smem 64KB: x transposed [k*16 + n].
// ---------------------------------------------------------------------------
__global__ __launch_bounds__(256, 2) void k1(
    const float* __restrict__ x, const float* __restrict__ W)
{
    extern __shared__ float s_x[];              // [k*16 + n], 65536 B

    const int tid = threadIdx.x;
    const int hb  = blockIdx.x >> 1;
    const int ch  = blockIdx.x & 1;
    const int b   = hb & 31;
    const int c0  = ch * 512 + tid * 2;

    const float* xb = x + (size_t)b * 14336;
    for (int idx = tid; idx < 14336; idx += 256) {
        int n = idx >> 10, k = idx & 1023;
        s_x[k * 16 + n] = xb[idx];
    }
    __syncthreads();

    const float* Wp = W + ((size_t)hb << 20) + c0;

    float2 acc[7][2];
    #pragma unroll
    for (int p = 0; p < 7; p++) {
        acc[p][0] = make_float2(0.f, 0.f);
        acc[p][1] = make_float2(0.f, 0.f);
    }

    float2 wc[8];
    #pragma unroll
    for (int u = 0; u < 8; u++)
        wc[u] = *(const float2*)(Wp + (size_t)u * 1024);

    #pragma unroll 1
    for (int k0 = 0; k0 < 1024; k0 += 8) {
        float2 wn[8];
        if (k0 + 8 < 1024) {
            #pragma unroll
            for (int u = 0; u < 8; u++)
                wn[u] = *(const float2*)(Wp + (size_t)(k0 + 8 + u) * 1024);
        }
        #pragma unroll
        for (int u = 0; u < 8; u++) {
            const float* xr = &s_x[(k0 + u) * 16];
            float4 xa = *(const float4*)(xr);
            float4 xb4 = *(const float4*)(xr + 4);
            float4 xc = *(const float4*)(xr + 8);
            float2 xd = *(const float2*)(xr + 12);
            float2 xp[7];
            xp[0] = make_float2(xa.x, xa.y);   xp[1] = make_float2(xa.z, xa.w);
            xp[2] = make_float2(xb4.x, xb4.y); xp[3] = make_float2(xb4.z, xb4.w);
            xp[4] = make_float2(xc.x, xc.y);   xp[5] = make_float2(xc.z, xc.w);
            xp[6] = xd;
            float2 s0 = make_float2(wc[u].x, wc[u].x);
            float2 s1 = make_float2(wc[u].y, wc[u].y);
            #pragma unroll
            for (int p = 0; p < 7; p++) {
                acc[p][0] = ffma2(xp[p], s0, acc[p][0]);
                acc[p][1] = ffma2(xp[p], s1, acc[p][1]);
            }
        }
        #pragma unroll
        for (int u = 0; u < 8; u++) wc[u] = wn[u];
    }

    float* dst = g_wh + (size_t)hb * 14336 + c0;
    #pragma unroll
    for (int p = 0; p < 7; p++) {
        *(float2*)(dst + (size_t)(2 * p) * 1024)     = make_float2(acc[p][0].x, acc[p][1].x);
        *(float2*)(dst + (size_t)(2 * p + 1) * 1024) = make_float2(acc[p][0].y, acc[p][1].y);
    }
}

// ---------------------------------------------------------------------------
// k1b (R6): grid 128 (hb), 256 threads.
// ---------------------------------------------------------------------------
__global__ __launch_bounds__(256, 1) void k1b(
    const float* __restrict__ adj, const float* __restrict__ a)
{
    __shared__ float s_red[8][28];
    __shared__ float s_dot[28];
    __shared__ float s_att[14 * 16];

    const int tid = threadIdx.x;
    const int hb  = blockIdx.x;
    const int b   = hb & 31;
    const int c0  = tid * 4;
    const int wid = tid >> 5, lane = tid & 31;

    float4 wh[14];
    const float* p0 = g_wh + (size_t)hb * 14336 + c0;
    #pragma unroll
    for (int n = 0; n < 14; n++)
        wh[n] = *(const float4*)(p0 + n * 1024);

    float4 a1 = *(const float4*)(a + (size_t)hb * 2048 + c0);
    float4 a2 = *(const float4*)(a + (size_t)hb * 2048 + 1024 + c0);
    float s1[14], s2[14];
    #pragma unroll
    for (int n = 0; n < 14; n++) {
        s1[n] = wh[n].x * a1.x + wh[n].y * a1.y + wh[n].z * a1.z + wh[n].w * a1.w;
        s2[n] = wh[n].x * a2.x + wh[n].y * a2.y + wh[n].z * a2.z + wh[n].w * a2.w;
    }
    #pragma unroll
    for (int n = 0; n < 14; n++) {
        #pragma unroll
        for (int off = 16; off > 0; off >>= 1) {
            s1[n] += __shfl_down_sync(0xFFFFFFFFu, s1[n], off);
            s2[n] += __shfl_down_sync(0xFFFFFFFFu, s2[n], off);
        }
    }
    if (lane == 0) {
        #pragma unroll
        for (int n = 0; n < 14; n++) { s_red[wid][n] = s1[n]; s_red[wid][14 + n] = s2[n]; }
    }
    __syncthreads();
    if (tid < 28) {
        float s = 0.f;
        #pragma unroll
        for (int w = 0; w < 8; w++) s += s_red[w][tid];
        s_dot[tid] = s;
    }
    __syncthreads();

    if (tid < 196) {
        int n = tid / 14, m = tid - n * 14;
        float e = s_dot[n] + s_dot[14 + m];
        e = (e > 0.f) ? e : 0.2f * e;
        float ad = adj[b * 196 + n * 14 + m];
        s_att[m * 16 + n] = (ad > 0.f) ? e : NEGC;
    }
    __syncthreads();

    if (tid < 14) {
        const int m = tid;
        float mx = -3.4e38f, ev[14], s = 0.f;
        #pragma unroll
        for (int n = 0; n < 14; n++) mx = fmaxf(mx, s_att[m * 16 + n]);
        #pragma unroll
        for (int n = 0; n < 14; n++) { ev[n] = expf(s_att[m * 16 + n] - mx); s += ev[n]; }
        float inv = 1.f / s;
        #pragma unroll
        for (int n = 0; n < 14; n++) s_att[m * 16 + n] = ev[n] * inv;
    }
    __syncthreads();

    float2 hp[7][4];
    #pragma unroll
    for (int p = 0; p < 7; p++)
        #pragma unroll
        for (int c = 0; c < 4; c++) hp[p][c] = make_float2(0.f, 0.f);

    #pragma unroll
    for (int m = 0; m < 14; m++) {
        float2 t0 = make_float2(wh[m].x, wh[m].x);
        float2 t1 = make_float2(wh[m].y, wh[m].y);
        float2 t2 = make_float2(wh[m].z, wh[m].z);
        float2 t3 = make_float2(wh[m].w, wh[m].w);
        #pragma unroll
        for (int p = 0; p < 7; p++) {
            float2 at = *(const float2*)&s_att[m * 16 + 2 * p];
            hp[p][0] = ffma2(at, t0, hp[p][0]);
            hp[p][1] = ffma2(at, t1, hp[p][1]);
            hp[p][2] = ffma2(at, t2, hp[p][2]);
            hp[p][3] = ffma2(at, t3, hp[p][3]);
        }
    }
    float* hpg = g_hp + (size_t)hb * 14336;
    #pragma unroll
    for (int p = 0; p < 7; p++) {
        *(float4*)&hpg[(2 * p) * 1024 + c0] =
            make_float4(hp[p][0].x, hp[p][1].x, hp[p][2].x, hp[p][3].x);
        *(float4*)&hpg[(2 * p + 1) * 1024 + c0] =
            make_float4(hp[p][0].y, hp[p][1].y, hp[p][2].y, hp[p][3].y);
    }
}

// ---------------------------------------------------------------------------
// k2: grid (128, 4) = (ks*4+ot, h), 128 threads.
// CTA tile: 256 o x 32 b, k-span 448 = 28 chunks of 16 k, double buffered.
// W staging: 4-lanes-per-row LDG.128 (8 wf/instr), transpose to s_w[k][SWP].
// hp staging: tid<64, 2 lanes per b-row (hko 0/8) -> ALL 32 b staged.
// Compute: thread = 8o x 8b.
// ---------------------------------------------------------------------------
#define SWP 262   // s_w row stride (floats): conflict-free STS pattern

__global__ __launch_bounds__(128, 4) void k2(const float* __restrict__ fcw)
{
    __shared__ float s_w[2][16 * SWP];
    __shared__ float s_hp[2][16 * 32];

    const int tid  = threadIdx.x;
    const int lane = tid & 31;
    const int w    = tid >> 5;                  // 0..3 -> b-group of 8
    const int ks   = blockIdx.x >> 2;           // 0..31
    const int ot   = blockIdx.x & 3;
    const int h    = blockIdx.y;
    const int obase = ot * 256;
    const int kbase = ks * 448;

    // W staging: row r0 = tid>>2 (+32g), k-segment (tid&3)*4
    const int r0   = tid >> 2;
    const int kseg = (tid & 3) * 4;
    const float* wbase = fcw + ((size_t)(h * 1024 + obase + r0)) * 14336 + kbase + kseg;

    // hp staging: tid<64; b = tid>>1 (0..31), k-offset (tid&1)*8
    const int hb_  = tid >> 1;
    const int hko  = (tid & 1) * 8;
    const float* hpb = g_hp + ((size_t)(h * 32 + hb_)) * 14336 + kbase + hko;

    float2 acc[4][8];
    #pragma unroll
    for (int q = 0; q < 4; q++)
        #pragma unroll
        for (int j = 0; j < 8; j++) acc[q][j] = make_float2(0.f, 0.f);

    // prologue: chunk 0 -> buffer 0
    {
        float4 vw[8];
        #pragma unroll
        for (int g = 0; g < 8; g++)
            vw[g] = *(const float4*)(wbase + (size_t)g * 32 * 14336);
        #pragma unroll
        for (int g = 0; g < 8; g++) {
            s_w[0][(kseg + 0) * SWP + r0 + 32 * g] = vw[g].x;
            s_w[0][(kseg + 1) * SWP + r0 + 32 * g] = vw[g].y;
            s_w[0][(kseg + 2) * SWP + r0 + 32 * g] = vw[g].z;
            s_w[0][(kseg + 3) * SWP + r0 + 32 * g] = vw[g].w;
        }
        if (tid < 64) {
            float4 h0 = *(const float4*)(hpb);
            float4 h1 = *(const float4*)(hpb + 4);
            float hh[8] = {h0.x, h0.y, h0.z, h0.w, h1.x, h1.y, h1.z, h1.w};
            #pragma unroll
            for (int i = 0; i < 8; i++)
                s_hp[0][(hko + i) * 32 + hb_] = hh[i];
        }
    }
    __syncthreads();

    #pragma unroll 1
    for (int ck = 0; ck < 28; ck++) {
        const int buf = ck & 1;

        float4 vw[8], h0, h1;
        if (ck + 1 < 28) {
            const float* wn = wbase + (ck + 1) * 16;
            #pragma unroll
            for (int g = 0; g < 8; g++)
                vw[g] = *(const float4*)(wn + (size_t)g * 32 * 14336);
            if (tid < 64) {
                h0 = *(const float4*)(hpb + (ck + 1) * 16);
                h1 = *(const float4*)(hpb + (ck + 1) * 16 + 4);
            }
        }

        #pragma unroll 4
        for (int k = 0; k < 16; k++) {
            float2 af[4];
            #pragma unroll
            for (int q = 0; q < 4; q++)
                af[q] = *(const float2*)&s_w[buf][k * SWP + 2 * lane + 64 * q];
            float4 bf0 = *(const float4*)&s_hp[buf][k * 32 + w * 8];
            float4 bf1 = *(const float4*)&s_hp[buf][k * 32 + w * 8 + 4];
            float bb[8] = {bf0.x, bf0.y, bf0.z, bf0.w, bf1.x, bf1.y, bf1.z, bf1.w};
            #pragma unroll
            for (int j = 0; j < 8; j++) {
                float2 d = make_float2(bb[j], bb[j]);
                #pragma unroll
                for (int q = 0; q < 4; q++)
                    acc[q][j] = ffma2(af[q], d, acc[q][j]);
            }
        }

        if (ck + 1 < 28) {
            const int nb = buf ^ 1;
            #pragma unroll
            for (int g = 0; g < 8; g++) {
                s_w[nb][(kseg + 0) * SWP + r0 + 32 * g] = vw[g].x;
                s_w[nb][(kseg + 1) * SWP + r0 + 32 * g] = vw[g].y;
                s_w[nb][(kseg + 2) * SWP + r0 + 32 * g] = vw[g].z;
                s_w[nb][(kseg + 3) * SWP + r0 + 32 * g] = vw[g].w;
            }
            if (tid < 64) {
                float hh[8] = {h0.x, h0.y, h0.z, h0.w, h1.x, h1.y, h1.z, h1.w};
                #pragma unroll
                for (int i = 0; i < 8; i++)
                    s_hp[nb][(hko + i) * 32 + hb_] = hh[i];
            }
            __syncthreads();
        }
    }

    float* dst = g_part + ((size_t)(h * 32 + ks)) * 32768 + obase;
    #pragma unroll
    for (int j = 0; j < 8; j++)
        #pragma unroll
        for (int q = 0; q < 4; q++)
            *(float2*)(dst + (size_t)(w * 8 + j) * 1024 + 2 * lane + 64 * q) = acc[q][j];
}

// ---------------------------------------------------------------------------
// k3a: reduce 128 partials + bias. grid 256, 128 threads.
// ---------------------------------------------------------------------------
__global__ __launch_bounds__(128, 8) void k3a(const float* __restrict__ fcb)
{
    const int b = blockIdx.x >> 3;
    const int o = (blockIdx.x & 7) * 128 + threadIdx.x;

    const float* p = g_part + b * 1024 + o;
    float s0 = 0.f, s1 = 0.f, s2 = 0.f, s3 = 0.f;
    #pragma unroll 8
    for (int pb = 0; pb < 128; pb += 4) {
        s0 += p[(size_t)pb * 32768];
        s1 += p[(size_t)(pb + 1) * 32768];
        s2 += p[(size_t)(pb + 2) * 32768];
        s3 += p[(size_t)(pb + 3) * 32768];
    }
    float s = (s0 + s1) + (s2 + s3)
            + fcb[o] + fcb[1024 + o] + fcb[2048 + o] + fcb[3072 + o];
    g_red[b * 1024 + o] = s;
}

// ---------------------------------------------------------------------------
// k3b: log_softmax per b. grid 32, 256 threads.
// ---------------------------------------------------------------------------
__global__ __launch_bounds__(256, 1) void k3b(float* __restrict__ out)
{
    __shared__ float red[256];
    const int b = blockIdx.x, tid = threadIdx.x;

    float4 v = *(const float4*)&g_red[b * 1024 + tid * 4];

    float mx = fmaxf(fmaxf(v.x, v.y), fmaxf(v.z, v.w));
    red[tid] = mx; __syncthreads();
    for (int st = 128; st > 0; st >>= 1) {
        if (tid < st) red[tid] = fmaxf(red[tid], red[tid + st]);
        __syncthreads();
    }
    mx = red[0]; __syncthreads();

    float s = expf(v.x - mx) + expf(v.y - mx) + expf(v.z - mx) + expf(v.w - mx);
    red[tid] = s; __syncthreads();
    for (int st = 128; st > 0; st >>= 1) {
        if (tid < st) red[tid] += red[tid + st];
        __syncthreads();
    }
    float lse = mx + logf(red[0]);

    *(float4*)&out[b * 1024 + tid * 4] =
        make_float4(v.x - lse, v.y - lse, v.z - lse, v.w - lse);
}

// ---------------------------------------------------------------------------
extern "C" void kernel_launch(void* const* d_in, const int* in_sizes, int n_in,
                              void* d_out, int out_size)
{
    const float *x = nullptr, *adj = nullptr, *W = nullptr, *a = nullptr,
                *fcw = nullptr, *fcb = nullptr;
    for (int i = 0; i < n_in; i++) {
        switch (in_sizes[i]) {
            case 32 * 14 * 1024:        x   = (const float*)d_in[i]; break;
            case 32 * 14 * 14:          adj = (const float*)d_in[i]; break;
            case 4 * 32 * 1024 * 1024:  W   = (const float*)d_in[i]; break;
            case 4 * 32 * 2048:         a   = (const float*)d_in[i]; break;
            case 4 * 1024 * 14336:      fcw = (const float*)d_in[i]; break;
            case 4 * 1024:              fcb = (const float*)d_in[i]; break;
            default: break;
        }
    }
    float* out = (float*)d_out;

    cudaFuncSetAttribute(k1, cudaFuncAttributeMaxDynamicSharedMemorySize, 65536);

    kdummy<<<1, 32>>>();
    k1<<<256, 256, 65536>>>(x, W);
    k1b<<<128, 256>>>(adj, a);
    k2<<<dim3(128, 4), 128>>>(fcw);
    k3a<<<256, 128>>>(fcb);
    k3b<<<32, 256>>>(out);
}